// round 13
// baseline (speedup 1.0000x reference)
#include <cuda_runtime.h>
#include <math.h>

#define Bc 4
#define Cc 64
#define Onc 64
#define Hc 128
#define Wc 128
#define HW (Hc*Wc)

// -------- scratch (device globals: allocation-free) --------
__device__ float  g_om[Bc*27*HW];       // offset-conv output (mask pre-sigmoided)
__device__ float  g_wT[576*Onc];        // dcn weights transposed [j][o]
__device__ float  g_pre[Bc*Onc*HW];     // pre-BN output
__device__ unsigned g_pk [Bc*9*HW];     // packed clamped corner coords, planes [b][k][pix]
__device__ float4 g_wt4[Bc*9*HW];       // bilinear weights (validity+mask folded), [b][k][pix]
__device__ float  g_scale[Onc];
__device__ float  g_shift[Onc];
__device__ float  g_psum[Onc*16];
__device__ float  g_psq[Onc*16];

// ---- packed fp32x2 helpers (Blackwell FFMA2, PTX-only) ----
__device__ __forceinline__ unsigned long long pack2(float lo, float hi) {
    unsigned long long r;
    asm("mov.b64 %0, {%1,%2};" : "=l"(r) : "f"(lo), "f"(hi));
    return r;
}
__device__ __forceinline__ void fma2(unsigned long long& d,
                                     unsigned long long a, unsigned long long b) {
    asm("fma.rn.f32x2 %0, %1, %2, %0;" : "+l"(d) : "l"(a), "l"(b));
}
__device__ __forceinline__ float2 unpack2(unsigned long long v) {
    float2 f;
    asm("mov.b64 {%0,%1}, %2;" : "=f"(f.x), "=f"(f.y) : "l"(v));
    return f;
}

// ---------------- kernel 0: transpose dcn weights [O][576] -> [576][O]
__global__ void k_transpose(const float* __restrict__ w) {
    int i = blockIdx.x*256 + threadIdx.x;
    if (i < Onc*576) {
        int o = i / 576, j = i - o*576;
        g_wT[j*Onc + o] = w[i];
    }
}

// ---------------- kernel 1: offset conv (27ch, 3x3, pad 1) + sigmoid on mask chans
__global__ void __launch_bounds__(128) k_offconv(const float* __restrict__ x,
                                                 const float* __restrict__ ow,
                                                 const float* __restrict__ ob) {
    extern __shared__ float wsh[]; // [c*9+k][28]
    int b = blockIdx.y;
    int tid = threadIdx.x;                // = w (0..127)
    for (int i = tid; i < 27*576; i += 128) {
        int oc = i / 576, r = i - oc*576;
        wsh[r*28 + oc] = ow[i];
    }
    __syncthreads();

    int w = tid;
    const float* xb = x + (long)b*Cc*HW;

    for (int hh = 0; hh < 2; hh++) {
        int h = blockIdx.x*2 + hh;

        unsigned long long acc2[14];
        #pragma unroll
        for (int q = 0; q < 14; q++) {
            float b0 = (2*q   < 27) ? __ldg(&ob[2*q])   : 0.f;
            float b1 = (2*q+1 < 27) ? __ldg(&ob[2*q+1]) : 0.f;
            acc2[q] = pack2(b0, b1);
        }

        for (int c = 0; c < Cc; c++) {
            const float* p = xb + c*HW;
            float v[9];
            #pragma unroll
            for (int dy = 0; dy < 3; dy++) {
                int yy = h - 1 + dy;
                bool yok = (unsigned)yy < (unsigned)Hc;
                const float* row = p + yy*Wc;
                v[dy*3+0] = (yok && w >= 1)    ? row[w-1] : 0.f;
                v[dy*3+1] =  yok               ? row[w]   : 0.f;
                v[dy*3+2] = (yok && w <= Wc-2) ? row[w+1] : 0.f;
            }
            #pragma unroll
            for (int k = 0; k < 9; k++) {
                unsigned long long vk2 = pack2(v[k], v[k]);
                const ulonglong2* wr = (const ulonglong2*)&wsh[(c*9+k)*28];
                #pragma unroll
                for (int q = 0; q < 7; q++) {
                    ulonglong2 wv = wr[q];
                    fma2(acc2[q*2+0], vk2, wv.x);
                    fma2(acc2[q*2+1], vk2, wv.y);
                }
            }
        }
        float accf[28];
        #pragma unroll
        for (int q = 0; q < 14; q++) {
            float2 u = unpack2(acc2[q]);
            accf[2*q] = u.x; accf[2*q+1] = u.y;
        }
        float* outp = g_om + ((long)b*27*HW) + h*Wc + w;
        #pragma unroll
        for (int oc = 0; oc < 27; oc++) {
            float vv = accf[oc];
            if (oc >= 18) vv = 1.f/(1.f + expf(-vv));   // sigmoid mask channels
            outp[oc*HW] = vv;
        }
    }
}

// ---------------- kernel 2: per-(pixel,tap) bilinear setup, fully coalesced (all batches)
__global__ void __launch_bounds__(256) k_prep() {
    int e = blockIdx.x*256 + threadIdx.x;      // over 4*9*HW
    if (e >= Bc*9*HW) return;
    int b   = e/(9*HW);
    int r   = e % (9*HW);
    int k   = r / HW;
    int pix = r % HW;
    int h = pix >> 7, w = pix & 127;

    const float* omb = g_om + (long)b*27*HW;
    float offx = omb[k*HW + pix];
    float offy = omb[(9+k)*HW + pix];
    float m    = omb[(18+k)*HW + pix];

    float py = (float)(h - 1 + k/3) + offy;
    float px = (float)(w - 1 + k%3) + offx;
    float y0f = floorf(py), x0f = floorf(px);
    float wy = py - y0f, wx = px - x0f;
    int y0 = (int)fmaxf(fminf(y0f, 1e6f), -1e6f);
    int x0 = (int)fmaxf(fminf(x0f, 1e6f), -1e6f);
    int y1 = y0 + 1, x1 = x0 + 1;
    float vy0 = (y0 >= 0 && y0 < Hc) ? 1.f : 0.f;
    float vy1 = (y1 >= 0 && y1 < Hc) ? 1.f : 0.f;
    float vx0 = (x0 >= 0 && x0 < Wc) ? 1.f : 0.f;
    float vx1 = (x1 >= 0 && x1 < Wc) ? 1.f : 0.f;
    float4 wv;
    wv.x = (1.f-wy)*(1.f-wx)*m*vy0*vx0;
    wv.y = (1.f-wy)*wx      *m*vy0*vx1;
    wv.z = wy      *(1.f-wx)*m*vy1*vx0;
    wv.w = wy      *wx      *m*vy1*vx1;
    int y0c = min(max(y0,0),Hc-1), y1c = min(max(y1,0),Hc-1);
    int x0c = min(max(x0,0),Wc-1), x1c = min(max(x1,0),Wc-1);

    int plane = b*9 + k;
    g_pk [plane*HW + pix] = (unsigned)y0c | ((unsigned)y1c<<8) | ((unsigned)x0c<<16) | ((unsigned)x1c<<24);
    g_wt4[plane*HW + pix] = wv;
}

// ---------------- kernel 3: fused sampling + GEMM. 128-pixel row tile, To=4 x Tp=8.
// weights read via __ldg from g_wT (L1-resident, shared across CTAs) -> smem 47.6KB, 4 CTAs/SM
__global__ void __launch_bounds__(256,4) k_dcn(const float* __restrict__ x,
                                               const float* __restrict__ dcn_b) {
    __shared__ float4   wt4_s[9*128];    // 18432B
    __shared__ float    s[48*128];       // 24576B
    __shared__ unsigned pk_s[9*128];     // 4608B   (total 47616B static)

    int h = blockIdx.x, b = blockIdx.y;
    int tid = threadIdx.x;

    // stage per-pixel bilinear setup as [k][pix] planes (coalesced both ways)
    {
        int base = h*Wc;
        for (int i = tid; i < 9*128; i += 256) {
            int k = i >> 7, pix = i & 127;
            int g = (b*9 + k)*HW + base + pix;
            pk_s [i] = g_pk[g];
            wt4_s[i] = g_wt4[g];
        }
    }
    __syncthreads();

    int pix = tid & 127, jset = tid >> 7;   // gather roles: 2 j-sets x 128 pixels
    int oi  = tid & 15,  pi   = tid >> 4;   // GEMM roles: o = oi*4.., pix = pi*8..
    const float* xb = x + (long)b*Cc*HW;

    unsigned long long acc2[4][4];          // [oq][pixpair]
    #pragma unroll
    for (int oq = 0; oq < 4; oq++) {
        float bo = __ldg(&dcn_b[oi*4 + oq]);
        unsigned long long bb = pack2(bo, bo);
        #pragma unroll
        for (int pp = 0; pp < 4; pp++) acc2[oq][pp] = bb;
    }

    for (int ch = 0; ch < 12; ch++) {
        // ---- gather 48 j's for 128 pixels (24 samples/thread) ----
        {
            int j0 = ch*48 + jset;
            int c = j0 / 9;
            int k = j0 - c*9;
            const float* xp = xb + c*HW;
            #pragma unroll 4
            for (int m = 0; m < 24; m++) {
                unsigned u = pk_s[k*128 + pix];
                float4 wv = wt4_s[k*128 + pix];
                int y0 = u & 255, y1 = (u>>8)&255, x0c = (u>>16)&255, x1c = u>>24;
                float v = wv.x * xp[y0*Wc + x0c]
                        + wv.y * xp[y0*Wc + x1c]
                        + wv.z * xp[y1*Wc + x0c]
                        + wv.w * xp[y1*Wc + x1c];
                s[(jset + 2*m)*128 + pix] = v;
                k += 2;
                if (k >= 9) { k -= 9; c++; xp += HW; }
            }
        }
        __syncthreads();

        // ---- GEMM on chunk: acc[4 o][8 pix] += wT[j][o] * s[j][pix] ----
        // w rows (256B each) hit in L1; shared by all warps + resident CTAs
        {
            const float*  sbase = s + pi*8;
            const float4* wbase = (const float4*)(g_wT + (long)ch*48*64 + oi*4);
            #pragma unroll 6
            for (int j = 0; j < 48; j++) {
                float4 w4 = __ldg(wbase + j*16);                          // 16 float4 = 64 floats
                ulonglong2 sA = *(const ulonglong2*)(sbase + j*128);      // pix 0-3
                ulonglong2 sB = *(const ulonglong2*)(sbase + j*128 + 4);  // pix 4-7
                float wq[4] = {w4.x, w4.y, w4.z, w4.w};
                #pragma unroll
                for (int oq = 0; oq < 4; oq++) {
                    unsigned long long wd = pack2(wq[oq], wq[oq]);
                    fma2(acc2[oq][0], sA.x, wd);
                    fma2(acc2[oq][1], sA.y, wd);
                    fma2(acc2[oq][2], sB.x, wd);
                    fma2(acc2[oq][3], sB.y, wd);
                }
            }
        }
        __syncthreads();
    }
    #pragma unroll
    for (int oq = 0; oq < 4; oq++) {
        float* op = g_pre + ((long)b*Onc + oi*4 + oq)*HW + h*Wc + pi*8;
        *(ulonglong2*)(op)     = make_ulonglong2(acc2[oq][0], acc2[oq][1]);
        *(ulonglong2*)(op + 4) = make_ulonglong2(acc2[oq][2], acc2[oq][3]);
    }
}

// ---------------- kernel 4a: partial per-channel sums (1024 blocks, deterministic)
__global__ void k_bnstats1() {
    __shared__ float r1[256], r2[256];
    int sl = blockIdx.x;       // 0..15 slice
    int o  = blockIdx.y;       // channel
    int tid = threadIdx.x;
    int b = sl >> 2, q = sl & 3;
    const float4* p = (const float4*)(g_pre + ((long)(b*Onc + o))*HW + q*4096);
    float sm = 0.f, sq = 0.f;
    #pragma unroll
    for (int i = tid; i < 1024; i += 256) {
        float4 v = p[i];
        sm += v.x + v.y + v.z + v.w;
        sq += v.x*v.x + v.y*v.y + v.z*v.z + v.w*v.w;
    }
    r1[tid] = sm; r2[tid] = sq; __syncthreads();
    for (int st = 128; st > 0; st >>= 1) {
        if (tid < st) { r1[tid] += r1[tid+st]; r2[tid] += r2[tid+st]; }
        __syncthreads();
    }
    if (tid == 0) { g_psum[o*16 + sl] = r1[0]; g_psq[o*16 + sl] = r2[0]; }
}

// ---------------- kernel 4b: finalize scale/shift
__global__ void k_bnstats2(const float* __restrict__ gamma, const float* __restrict__ beta) {
    int o = threadIdx.x;
    float sm = 0.f, sq = 0.f;
    #pragma unroll
    for (int i = 0; i < 16; i++) { sm += g_psum[o*16+i]; sq += g_psq[o*16+i]; }
    float n   = (float)(Bc*HW);
    float mu  = sm/n;
    float var = sq/n - mu*mu;
    float sc  = __ldg(&gamma[o]) * rsqrtf(var + 1e-5f);
    g_scale[o] = sc;
    g_shift[o] = __ldg(&beta[o]) - mu*sc;
}

// ---------------- kernel 5: BN apply + ReLU
__global__ void k_bnapply(float* __restrict__ out) {
    int i = blockIdx.x*256 + threadIdx.x;  // float4 index
    int e = i*4;
    int o = (e >> 14) & 63;                // plane = 16384 elems
    float4 v = *(const float4*)(g_pre + e);
    float sc = g_scale[o], sf = g_shift[o];
    float4 r;
    r.x = fmaxf(fmaf(v.x, sc, sf), 0.f);
    r.y = fmaxf(fmaf(v.y, sc, sf), 0.f);
    r.z = fmaxf(fmaf(v.z, sc, sf), 0.f);
    r.w = fmaxf(fmaf(v.w, sc, sf), 0.f);
    *(float4*)(out + e) = r;
}

extern "C" void kernel_launch(void* const* d_in, const int* in_sizes, int n_in,
                              void* d_out, int out_size) {
    const float* x  = (const float*)d_in[0];
    const float* ow = (const float*)d_in[1];
    const float* ob = (const float*)d_in[2];
    const float* dw = (const float*)d_in[3];
    const float* db = (const float*)d_in[4];
    const float* ga = (const float*)d_in[5];
    const float* be = (const float*)d_in[6];
    float* out = (float*)d_out;

    cudaFuncSetAttribute(k_offconv, cudaFuncAttributeMaxDynamicSharedMemorySize, 576*28*4);

    k_transpose<<<144, 256>>>(dw);                          // launch 0

    dim3 g1(Hc/2, Bc);
    k_offconv<<<g1, 128, 576*28*4>>>(x, ow, ob);            // launch 1

    k_prep<<<(Bc*9*HW + 255)/256, 256>>>();                 // launch 2

    dim3 g2(Hc, Bc);
    k_dcn<<<g2, 256>>>(x, db);                              // launch 3 (ncu capture slot)

    dim3 g3(16, Onc);
    k_bnstats1<<<g3, 256>>>();                              // launch 4
    k_bnstats2<<<1, Onc>>>(ga, be);                         // launch 5

    k_bnapply<<<(Bc*Onc*HW)/4/256, 256>>>(out);             // launch 6
}

// round 16
// speedup vs baseline: 1.2768x; 1.2768x over previous
#include <cuda_runtime.h>
#include <math.h>

#define Bc 4
#define Cc 64
#define Onc 64
#define Hc 128
#define Wc 128
#define HW (Hc*Wc)
#define SS 132   // s row stride (floats): 16B-aligned, conflict-free B-frag loads

// -------- scratch (device globals: allocation-free) --------
__device__ float  g_om[Bc*27*HW];        // offset-conv output (mask pre-sigmoided)
__device__ float  g_wfrag[4*72*32*4];    // tf32 A-fragments [otile][kstep][lane]{a0..a3}
__device__ float  g_pre[Bc*Onc*HW];      // pre-BN output
__device__ unsigned g_pk [Bc*9*HW];      // packed clamped corner coords [b][k][pix]
__device__ float4 g_wt4[Bc*9*HW];        // bilinear weights (validity+mask folded)
__device__ float  g_scale[Onc];
__device__ float  g_shift[Onc];
__device__ float  g_psum[Onc*16];
__device__ float  g_psq[Onc*16];

// ---- packed fp32x2 helpers (Blackwell FFMA2, PTX-only) ----
__device__ __forceinline__ unsigned long long pack2(float lo, float hi) {
    unsigned long long r;
    asm("mov.b64 %0, {%1,%2};" : "=l"(r) : "f"(lo), "f"(hi));
    return r;
}
__device__ __forceinline__ void fma2(unsigned long long& d,
                                     unsigned long long a, unsigned long long b) {
    asm("fma.rn.f32x2 %0, %1, %2, %0;" : "+l"(d) : "l"(a), "l"(b));
}
__device__ __forceinline__ float2 unpack2(unsigned long long v) {
    float2 f;
    asm("mov.b64 {%0,%1}, %2;" : "=f"(f.x), "=f"(f.y) : "l"(v));
    return f;
}
__device__ __forceinline__ float to_tf32(float v) {
    float r;
    asm("cvt.rna.tf32.f32 %0, %1;" : "=f"(r) : "f"(v));
    return r;
}
__device__ __forceinline__ void mma_tf32(float* d, const float4& a,
                                         unsigned b0, unsigned b1) {
    asm volatile(
        "mma.sync.aligned.m16n8k8.row.col.f32.tf32.tf32.f32 "
        "{%0,%1,%2,%3}, {%4,%5,%6,%7}, {%8,%9}, {%0,%1,%2,%3};"
        : "+f"(d[0]), "+f"(d[1]), "+f"(d[2]), "+f"(d[3])
        : "r"(__float_as_uint(a.x)), "r"(__float_as_uint(a.y)),
          "r"(__float_as_uint(a.z)), "r"(__float_as_uint(a.w)),
          "r"(b0), "r"(b1));
}

// ---------------- kernel 0: build tf32 A-fragments from dcn weights
// A[m][k] = wT[j][o] = dw[o*576 + j];  j = kstep*8 + {tig, tig+4}, o = otile*16 + {gid, gid+8}
__global__ void k_wfrag(const float* __restrict__ dw) {
    int t = blockIdx.x*256 + threadIdx.x;
    if (t >= 4*72*32) return;
    int lane = t & 31;
    int rest = t >> 5;
    int kstep = rest % 72;
    int ot = rest / 72;
    int gid = lane >> 2, tig = lane & 3;
    int olo = ot*16 + gid, ohi = olo + 8;
    int jlo = kstep*8 + tig, jhi = jlo + 4;
    float4 a;
    a.x = to_tf32(dw[olo*576 + jlo]);
    a.y = to_tf32(dw[ohi*576 + jlo]);
    a.z = to_tf32(dw[olo*576 + jhi]);
    a.w = to_tf32(dw[ohi*576 + jhi]);
    ((float4*)g_wfrag)[t] = a;
}

// ---------------- kernel 1: offset conv (27ch, 3x3, pad 1) + sigmoid on mask chans
__global__ void __launch_bounds__(128) k_offconv(const float* __restrict__ x,
                                                 const float* __restrict__ ow,
                                                 const float* __restrict__ ob) {
    extern __shared__ float wsh[]; // [c*9+k][28]
    int b = blockIdx.y;
    int tid = threadIdx.x;                // = w (0..127)
    for (int i = tid; i < 27*576; i += 128) {
        int oc = i / 576, r = i - oc*576;
        wsh[r*28 + oc] = ow[i];
    }
    __syncthreads();

    int w = tid;
    const float* xb = x + (long)b*Cc*HW;

    for (int hh = 0; hh < 2; hh++) {
        int h = blockIdx.x*2 + hh;

        unsigned long long acc2[14];
        #pragma unroll
        for (int q = 0; q < 14; q++) {
            float b0 = (2*q   < 27) ? __ldg(&ob[2*q])   : 0.f;
            float b1 = (2*q+1 < 27) ? __ldg(&ob[2*q+1]) : 0.f;
            acc2[q] = pack2(b0, b1);
        }

        for (int c = 0; c < Cc; c++) {
            const float* p = xb + c*HW;
            float v[9];
            #pragma unroll
            for (int dy = 0; dy < 3; dy++) {
                int yy = h - 1 + dy;
                bool yok = (unsigned)yy < (unsigned)Hc;
                const float* row = p + yy*Wc;
                v[dy*3+0] = (yok && w >= 1)    ? row[w-1] : 0.f;
                v[dy*3+1] =  yok               ? row[w]   : 0.f;
                v[dy*3+2] = (yok && w <= Wc-2) ? row[w+1] : 0.f;
            }
            #pragma unroll
            for (int k = 0; k < 9; k++) {
                unsigned long long vk2 = pack2(v[k], v[k]);
                const ulonglong2* wr = (const ulonglong2*)&wsh[(c*9+k)*28];
                #pragma unroll
                for (int q = 0; q < 7; q++) {
                    ulonglong2 wv = wr[q];
                    fma2(acc2[q*2+0], vk2, wv.x);
                    fma2(acc2[q*2+1], vk2, wv.y);
                }
            }
        }
        float accf[28];
        #pragma unroll
        for (int q = 0; q < 14; q++) {
            float2 u = unpack2(acc2[q]);
            accf[2*q] = u.x; accf[2*q+1] = u.y;
        }
        float* outp = g_om + ((long)b*27*HW) + h*Wc + w;
        #pragma unroll
        for (int oc = 0; oc < 27; oc++) {
            float vv = accf[oc];
            if (oc >= 18) vv = 1.f/(1.f + expf(-vv));   // sigmoid mask channels
            outp[oc*HW] = vv;
        }
    }
}

// ---------------- kernel 2: per-(pixel,tap) bilinear setup, fully coalesced
__global__ void __launch_bounds__(256) k_prep() {
    int e = blockIdx.x*256 + threadIdx.x;      // over 4*9*HW
    if (e >= Bc*9*HW) return;
    int b   = e/(9*HW);
    int r   = e % (9*HW);
    int k   = r / HW;
    int pix = r % HW;
    int h = pix >> 7, w = pix & 127;

    const float* omb = g_om + (long)b*27*HW;
    float offx = omb[k*HW + pix];
    float offy = omb[(9+k)*HW + pix];
    float m    = omb[(18+k)*HW + pix];

    float py = (float)(h - 1 + k/3) + offy;
    float px = (float)(w - 1 + k%3) + offx;
    float y0f = floorf(py), x0f = floorf(px);
    float wy = py - y0f, wx = px - x0f;
    int y0 = (int)fmaxf(fminf(y0f, 1e6f), -1e6f);
    int x0 = (int)fmaxf(fminf(x0f, 1e6f), -1e6f);
    int y1 = y0 + 1, x1 = x0 + 1;
    float vy0 = (y0 >= 0 && y0 < Hc) ? 1.f : 0.f;
    float vy1 = (y1 >= 0 && y1 < Hc) ? 1.f : 0.f;
    float vx0 = (x0 >= 0 && x0 < Wc) ? 1.f : 0.f;
    float vx1 = (x1 >= 0 && x1 < Wc) ? 1.f : 0.f;
    float4 wv;
    wv.x = (1.f-wy)*(1.f-wx)*m*vy0*vx0;
    wv.y = (1.f-wy)*wx      *m*vy0*vx1;
    wv.z = wy      *(1.f-wx)*m*vy1*vx0;
    wv.w = wy      *wx      *m*vy1*vx1;
    int y0c = min(max(y0,0),Hc-1), y1c = min(max(y1,0),Hc-1);
    int x0c = min(max(x0,0),Wc-1), x1c = min(max(x1,0),Wc-1);

    int plane = b*9 + k;
    g_pk [plane*HW + pix] = (unsigned)y0c | ((unsigned)y1c<<8) | ((unsigned)x0c<<16) | ((unsigned)x1c<<24);
    g_wt4[plane*HW + pix] = wv;
}

// ---------------- kernel 3: fused sampling + tf32-MMA GEMM. 128-pixel row tile.
// warp tile: 16 o x 64 pix; 8 warps = 4 o-tiles x 2 pix-halves
__global__ void __launch_bounds__(256,4) k_dcn(const float* __restrict__ x,
                                               const float* __restrict__ dcn_b) {
    __shared__ float    s[48*SS];        // 25344B  (rows = j within chunk, tf32 values)
    __shared__ float4   wt4_s[9*128];    // 18432B
    __shared__ unsigned pk_s[9*128];     // 4608B   (total 48384B static)

    int h = blockIdx.x, b = blockIdx.y;
    int tid = threadIdx.x;

    // stage per-pixel bilinear setup as [k][pix] planes
    {
        int base = h*Wc;
        for (int i = tid; i < 9*128; i += 256) {
            int k = i >> 7, pix = i & 127;
            int g = (b*9 + k)*HW + base + pix;
            pk_s [i] = g_pk[g];
            wt4_s[i] = g_wt4[g];
        }
    }
    __syncthreads();

    int pix = tid & 127, jset = tid >> 7;   // gather roles
    int warp = tid >> 5, lane = tid & 31;   // GEMM roles
    int gid = lane >> 2, tig = lane & 3;
    int o0 = (warp & 3)*16, p0 = (warp >> 2)*64;
    const float* xb = x + (long)b*Cc*HW;

    float acc[8][4];
    {
        float blo = __ldg(&dcn_b[o0 + gid]);
        float bhi = __ldg(&dcn_b[o0 + gid + 8]);
        #pragma unroll
        for (int nt = 0; nt < 8; nt++) {
            acc[nt][0] = blo; acc[nt][1] = blo;
            acc[nt][2] = bhi; acc[nt][3] = bhi;
        }
    }

    for (int ch = 0; ch < 12; ch++) {
        // ---- gather 48 j's for 128 pixels (24 samples/thread), tf32-convert ----
        {
            int j0 = ch*48 + jset;
            int c = j0 / 9;
            int k = j0 - c*9;
            const float* xp = xb + c*HW;
            #pragma unroll 4
            for (int m = 0; m < 24; m++) {
                unsigned u = pk_s[k*128 + pix];
                float4 wv = wt4_s[k*128 + pix];
                int y0 = u & 255, y1 = (u>>8)&255, x0c = (u>>16)&255, x1c = u>>24;
                float v = wv.x * xp[y0*Wc + x0c]
                        + wv.y * xp[y0*Wc + x1c]
                        + wv.z * xp[y1*Wc + x0c]
                        + wv.w * xp[y1*Wc + x1c];
                s[(jset + 2*m)*SS + pix] = to_tf32(v);
                k += 2;
                if (k >= 9) { k -= 9; c++; xp += HW; }
            }
        }
        __syncthreads();

        // ---- MMA on chunk: 6 k-steps of K=8 ----
        {
            #pragma unroll
            for (int ks = 0; ks < 6; ks++) {
                int kstep = ch*6 + ks;
                float4 af = __ldg((const float4*)&g_wfrag[4*(((warp & 3)*72 + kstep)*32 + lane)]);
                const float* r0 = s + (ks*8 + tig)*SS + p0 + gid;
                const float* r1 = r0 + 4*SS;
                #pragma unroll
                for (int nt = 0; nt < 8; nt++) {
                    unsigned b0 = __float_as_uint(r0[nt*8]);
                    unsigned b1 = __float_as_uint(r1[nt*8]);
                    mma_tf32(acc[nt], af, b0, b1);
                }
            }
        }
        __syncthreads();
    }

    // epilogue: D[gid][2tig..], D[gid+8][2tig..] per n-tile
    #pragma unroll
    for (int nt = 0; nt < 8; nt++) {
        long base = ((long)b*Onc + o0 + gid)*HW + h*Wc + p0 + nt*8 + 2*tig;
        *(float2*)&g_pre[base]        = make_float2(acc[nt][0], acc[nt][1]);
        *(float2*)&g_pre[base + 8*HW] = make_float2(acc[nt][2], acc[nt][3]);
    }
}

// ---------------- kernel 4a: partial per-channel sums (1024 blocks, deterministic)
__global__ void k_bnstats1() {
    __shared__ float r1[256], r2[256];
    int sl = blockIdx.x;       // 0..15 slice
    int o  = blockIdx.y;       // channel
    int tid = threadIdx.x;
    int b = sl >> 2, q = sl & 3;
    const float4* p = (const float4*)(g_pre + ((long)(b*Onc + o))*HW + q*4096);
    float sm = 0.f, sq = 0.f;
    #pragma unroll
    for (int i = tid; i < 1024; i += 256) {
        float4 v = p[i];
        sm += v.x + v.y + v.z + v.w;
        sq += v.x*v.x + v.y*v.y + v.z*v.z + v.w*v.w;
    }
    r1[tid] = sm; r2[tid] = sq; __syncthreads();
    for (int st = 128; st > 0; st >>= 1) {
        if (tid < st) { r1[tid] += r1[tid+st]; r2[tid] += r2[tid+st]; }
        __syncthreads();
    }
    if (tid == 0) { g_psum[o*16 + sl] = r1[0]; g_psq[o*16 + sl] = r2[0]; }
}

// ---------------- kernel 4b: finalize scale/shift
__global__ void k_bnstats2(const float* __restrict__ gamma, const float* __restrict__ beta) {
    int o = threadIdx.x;
    float sm = 0.f, sq = 0.f;
    #pragma unroll
    for (int i = 0; i < 16; i++) { sm += g_psum[o*16+i]; sq += g_psq[o*16+i]; }
    float n   = (float)(Bc*HW);
    float mu  = sm/n;
    float var = sq/n - mu*mu;
    float sc  = __ldg(&gamma[o]) * rsqrtf(var + 1e-5f);
    g_scale[o] = sc;
    g_shift[o] = __ldg(&beta[o]) - mu*sc;
}

// ---------------- kernel 5: BN apply + ReLU
__global__ void k_bnapply(float* __restrict__ out) {
    int i = blockIdx.x*256 + threadIdx.x;  // float4 index
    int e = i*4;
    int o = (e >> 14) & 63;                // plane = 16384 elems
    float4 v = *(const float4*)(g_pre + e);
    float sc = g_scale[o], sf = g_shift[o];
    float4 r;
    r.x = fmaxf(fmaf(v.x, sc, sf), 0.f);
    r.y = fmaxf(fmaf(v.y, sc, sf), 0.f);
    r.z = fmaxf(fmaf(v.z, sc, sf), 0.f);
    r.w = fmaxf(fmaf(v.w, sc, sf), 0.f);
    *(float4*)(out + e) = r;
}

extern "C" void kernel_launch(void* const* d_in, const int* in_sizes, int n_in,
                              void* d_out, int out_size) {
    const float* x  = (const float*)d_in[0];
    const float* ow = (const float*)d_in[1];
    const float* ob = (const float*)d_in[2];
    const float* dw = (const float*)d_in[3];
    const float* db = (const float*)d_in[4];
    const float* ga = (const float*)d_in[5];
    const float* be = (const float*)d_in[6];
    float* out = (float*)d_out;

    cudaFuncSetAttribute(k_offconv, cudaFuncAttributeMaxDynamicSharedMemorySize, 576*28*4);

    k_wfrag<<<36, 256>>>(dw);                               // launch 0

    dim3 g1(Hc/2, Bc);
    k_offconv<<<g1, 128, 576*28*4>>>(x, ow, ob);            // launch 1

    k_prep<<<(Bc*9*HW + 255)/256, 256>>>();                 // launch 2

    dim3 g2(Hc, Bc);
    k_dcn<<<g2, 256>>>(x, db);                              // launch 3 (ncu capture slot)

    dim3 g3(16, Onc);
    k_bnstats1<<<g3, 256>>>();                              // launch 4
    k_bnstats2<<<1, Onc>>>(ga, be);                         // launch 5

    k_bnapply<<<(Bc*Onc*HW)/4/256, 256>>>(out);             // launch 6
}